// round 1
// baseline (speedup 1.0000x reference)
#include <cuda_runtime.h>
#include <cuda_bf16.h>
#include <math.h>

// ---------------- problem constants ----------------
#define NN    20000
#define EE    400000
#define BB    200
#define HH    10
#define FF    78
#define HID   780          // HH*FF
#define SEQ   1000
#define VOC   26
#define EMB   128
#define NF    32
#define KS    8
#define CONV_OUT 993       // SEQ-KS+1
#define CONVF (NF*CONV_OUT)   // 31776

// ---------------- scratch (device globals; no runtime allocation) ----------------
__device__ float g_h   [(size_t)NN*HID];
__device__ float g_as  [NN*HH];
__device__ float g_ad  [NN*HH];
__device__ float g_x1  [(size_t)NN*HID];
__device__ float g_h2  [(size_t)NN*HID];
__device__ int   g_deg [NN];
__device__ float g_dinv[NN];
__device__ int   g_rowstart[NN+1];
__device__ int   g_cursor[NN];
__device__ int   g_csr [EE];
__device__ float g_xg  [BB*HID];
__device__ float g_g1  [BB*1500];
__device__ float g_xc  [BB*256];
__device__ float g_P   [VOC*NF*KS];
__device__ float g_convf[(size_t)BB*CONVF];
__device__ float g_b1  [BB*1024];
__device__ float g_b2  [BB*512];
__device__ float g_b3  [BB*256];
__device__ float g_b4  [BB*128];

__device__ __forceinline__ float lrelu(float x){ return x > 0.f ? x : 0.2f*x; }

// ---------------- generic tiled fp32 GEMM:  C[M,N] = A[M,K] @ B[K,N] (+bias)(+relu) ----------------
// ATOMIC=true: split-K partials atomically added into pre-zeroed C (bias added by z==0).
template<bool RELU, bool ATOMIC>
__global__ void gemm_k(const float* __restrict__ A, const float* __restrict__ Bm,
                       const float* __restrict__ bias, float* __restrict__ C,
                       int M, int N, int K, int ldc, int kPerSplit)
{
    const int BM = 64, BN = 64, BK = 16;
    __shared__ float As[BK][BM+1];
    __shared__ float Bs[BK][BN+1];
    const int tid = threadIdx.x;                 // 256 threads
    const int brow = blockIdx.y * BM;
    const int bcol = blockIdx.x * BN;
    const int kz0 = blockIdx.z * kPerSplit;
    const int kz1 = min(K, kz0 + kPerSplit);
    const int tr = (tid >> 4) * 4;               // 0..60
    const int tc = (tid & 15) * 4;               // 0..60
    float acc[4][4];
    #pragma unroll
    for (int i=0;i<4;i++)
        #pragma unroll
        for (int j=0;j<4;j++) acc[i][j]=0.f;

    for (int k0 = kz0; k0 < kz1; k0 += BK) {
        #pragma unroll
        for (int i=0;i<4;i++){
            int idx = tid + i*256;
            int r = idx >> 4, c = idx & 15;      // A tile BMxBK
            int gr = brow + r, gc = k0 + c;
            float v = 0.f;
            if (gr < M && gc < kz1) v = A[(size_t)gr*K + gc];
            As[c][r] = v;
        }
        #pragma unroll
        for (int i=0;i<4;i++){
            int idx = tid + i*256;
            int r = idx >> 6, c = idx & 63;      // B tile BKxBN
            int gr = k0 + r, gc = bcol + c;
            float v = 0.f;
            if (gr < kz1 && gc < N) v = Bm[(size_t)gr*N + gc];
            Bs[r][c] = v;
        }
        __syncthreads();
        #pragma unroll
        for (int kk=0; kk<BK; kk++){
            float ra[4], rb[4];
            #pragma unroll
            for (int i=0;i<4;i++) ra[i] = As[kk][tr+i];
            #pragma unroll
            for (int j=0;j<4;j++) rb[j] = Bs[kk][tc+j];
            #pragma unroll
            for (int i=0;i<4;i++)
                #pragma unroll
                for (int j=0;j<4;j++) acc[i][j] = fmaf(ra[i], rb[j], acc[i][j]);
        }
        __syncthreads();
    }
    #pragma unroll
    for (int i=0;i<4;i++){
        int r = brow + tr + i;
        if (r >= M) continue;
        #pragma unroll
        for (int j=0;j<4;j++){
            int c = bcol + tc + j;
            if (c >= N) continue;
            float v = acc[i][j];
            if (ATOMIC) {
                if (blockIdx.z == 0 && bias) v += bias[c];
                atomicAdd(&C[(size_t)r*ldc + c], v);
            } else {
                if (bias) v += bias[c];
                if (RELU) v = fmaxf(v, 0.f);
                C[(size_t)r*ldc + c] = v;
            }
        }
    }
}

// ---------------- misc small kernels ----------------
__global__ void zero_f(float* p, int n){ int i = blockIdx.x*blockDim.x + threadIdx.x; if (i<n) p[i]=0.f; }
__global__ void zero_i(int* p, int n){ int i = blockIdx.x*blockDim.x + threadIdx.x; if (i<n) p[i]=0; }

// attention coefficients: a_s[n,h], a_d[n,h]  (one warp per (n,h))
__global__ void gat_attn_k(const float* __restrict__ a_src, const float* __restrict__ a_dst)
{
    int w = (blockIdx.x*blockDim.x + threadIdx.x) >> 5;
    int lane = threadIdx.x & 31;
    if (w >= NN*HH) return;
    int n = w / HH, hh = w % HH;
    const float* hp = g_h + (size_t)n*HID + hh*FF;
    float s1 = 0.f, s2 = 0.f;
    for (int f = lane; f < FF; f += 32){
        float v = hp[f];
        s1 = fmaf(v, a_src[hh*FF + f], s1);
        s2 = fmaf(v, a_dst[hh*FF + f], s2);
    }
    #pragma unroll
    for (int o=16;o;o>>=1){ s1 += __shfl_xor_sync(0xffffffffu, s1, o); s2 += __shfl_xor_sync(0xffffffffu, s2, o); }
    if (lane == 0){ g_as[w] = s1; g_ad[w] = s2; }
}

__global__ void deg_k(const int* __restrict__ ei){
    int e = blockIdx.x*blockDim.x + threadIdx.x;
    if (e >= EE) return;
    atomicAdd(&g_deg[ei[EE + e]], 1);
}

// single-block exclusive scan over degrees; also fills cursor, dinv, row_start[NN]
__global__ void scan_k(){
    __shared__ int part[1024];
    int tid = threadIdx.x;
    const int CH = (NN + 1023) / 1024;
    int base = tid * CH;
    int s = 0;
    for (int i=0;i<CH;i++){ int idx = base+i; if (idx < NN) s += g_deg[idx]; }
    part[tid] = s;
    __syncthreads();
    for (int off=1; off<1024; off<<=1){
        int v = 0;
        if (tid >= off) v = part[tid - off];
        __syncthreads();
        part[tid] += v;
        __syncthreads();
    }
    int run = (tid == 0) ? 0 : part[tid-1];
    for (int i=0;i<CH;i++){
        int idx = base + i;
        if (idx < NN){
            g_rowstart[idx] = run;
            g_cursor[idx]   = run;
            int d = g_deg[idx];
            run += d;
            g_dinv[idx] = rsqrtf((float)(d + 1));   // +1 self loop; always >= 1
        }
    }
    if (tid == 1023) g_rowstart[NN] = part[1023];
}

__global__ void fill_k(const int* __restrict__ ei){
    int e = blockIdx.x*blockDim.x + threadIdx.x;
    if (e >= EE) return;
    int d = ei[EE + e];
    int pos = atomicAdd(&g_cursor[d], 1);
    g_csr[pos] = ei[e];
}

// GAT softmax-aggregate: one warp per (node, head); writes x1 = relu(agg + gat_b)
__global__ void gat_agg_k(const float* __restrict__ gat_b)
{
    int w = (blockIdx.x*blockDim.x + threadIdx.x) >> 5;
    int lane = threadIdx.x & 31;
    if (w >= NN*HH) return;
    int n = w / HH, hh = w % HH;
    int rs = g_rowstart[n], re = g_rowstart[n+1];
    float adn = g_ad[n*HH + hh];
    float eself = lrelu(g_as[n*HH + hh] + adn);
    // pass 1: max
    float m = eself;
    for (int i = rs + lane; i < re; i += 32){
        int s = g_csr[i];
        m = fmaxf(m, lrelu(g_as[s*HH + hh] + adn));
    }
    #pragma unroll
    for (int o=16;o;o>>=1) m = fmaxf(m, __shfl_xor_sync(0xffffffffu, m, o));
    // pass 2: denominator
    float den = 0.f;
    for (int i = rs + lane; i < re; i += 32){
        int s = g_csr[i];
        den += __expf(lrelu(g_as[s*HH + hh] + adn) - m);
    }
    #pragma unroll
    for (int o=16;o;o>>=1) den += __shfl_xor_sync(0xffffffffu, den, o);
    den += __expf(eself - m);
    // pass 3: weighted feature sum (lanes over F)
    const int hb = hh * FF;
    float acc0, acc1, acc2 = 0.f;
    {
        float wgt = __expf(eself - m);
        const float* hp = g_h + (size_t)n*HID + hb;
        acc0 = wgt * hp[lane];
        acc1 = wgt * hp[lane + 32];
        if (lane + 64 < FF) acc2 = wgt * hp[lane + 64];
    }
    for (int i = rs; i < re; i++){
        int s = g_csr[i];
        float wgt = __expf(lrelu(g_as[s*HH + hh] + adn) - m);
        const float* hp = g_h + (size_t)s*HID + hb;
        acc0 = fmaf(wgt, hp[lane], acc0);
        acc1 = fmaf(wgt, hp[lane + 32], acc1);
        if (lane + 64 < FF) acc2 = fmaf(wgt, hp[lane + 64], acc2);
    }
    float inv = 1.f / den;
    float* xp = g_x1 + (size_t)n*HID + hb;
    xp[lane]      = fmaxf(acc0*inv + gat_b[hb + lane], 0.f);
    xp[lane + 32] = fmaxf(acc1*inv + gat_b[hb + lane + 32], 0.f);
    if (lane + 64 < FF) xp[lane + 64] = fmaxf(acc2*inv + gat_b[hb + lane + 64], 0.f);
}

// GCN aggregate + fused global-add-pool: one block (256 thr) per node
__global__ void gcn_agg_pool_k(const float* __restrict__ gcn_b, const int* __restrict__ batch)
{
    int n = blockIdx.x;
    int tid = threadIdx.x;
    int rs = g_rowstart[n], re = g_rowstart[n+1];
    float dn = g_dinv[n];
    float acc[4] = {0.f,0.f,0.f,0.f};
    {   // self loop
        float nm = dn * dn;
        const float* hp = g_h2 + (size_t)n*HID;
        #pragma unroll
        for (int k=0;k<4;k++){ int f = tid + k*256; if (f < HID) acc[k] = fmaf(nm, hp[f], acc[k]); }
    }
    for (int i = rs; i < re; i++){
        int s = g_csr[i];
        float nm = g_dinv[s] * dn;
        const float* hp = g_h2 + (size_t)s*HID;
        #pragma unroll
        for (int k=0;k<4;k++){ int f = tid + k*256; if (f < HID) acc[k] = fmaf(nm, hp[f], acc[k]); }
    }
    int b = batch[n];
    float* xp = g_xg + (size_t)b*HID;
    #pragma unroll
    for (int k=0;k<4;k++){
        int f = tid + k*256;
        if (f < HID) atomicAdd(&xp[f], fmaxf(acc[k] + gcn_b[f], 0.f));
    }
}

// protein: P[v,nf,k] = sum_e emb[v,e]*cW[nf,e,k]
__global__ void protein_P_k(const float* __restrict__ emb, const float* __restrict__ cW)
{
    int idx = blockIdx.x*blockDim.x + threadIdx.x;
    if (idx >= VOC*NF*KS) return;
    int k  = idx % KS;
    int nf = (idx / KS) % NF;
    int v  = idx / (KS*NF);
    float s = 0.f;
    for (int e=0;e<EMB;e++) s = fmaf(emb[v*EMB + e], cW[(nf*EMB + e)*KS + k], s);
    g_P[idx] = s;
}

// conv via table lookup: convf[b, nf*993+t] = cb[nf] + sum_k P[tok[b,t+k],nf,k]
__global__ void conv_k(const int* __restrict__ target, const float* __restrict__ cb)
{
    int idx = blockIdx.x*blockDim.x + threadIdx.x;
    if (idx >= BB*NF*CONV_OUT) return;
    int t  = idx % CONV_OUT;
    int nf = (idx / CONV_OUT) % NF;
    int b  = idx / (CONV_OUT*NF);
    const int* tb = target + b*SEQ;
    float s = cb[nf];
    #pragma unroll
    for (int k=0;k<KS;k++) s += g_P[(tb[t+k]*NF + nf)*KS + k];
    g_convf[(size_t)b*CONVF + nf*CONV_OUT + t] = s;
}

// final: out[b] = dot(b4[b,:], oW) + ob  (one warp per b)
__global__ void out_k(const float* __restrict__ oW, const float* __restrict__ ob, float* __restrict__ out)
{
    int w = (blockIdx.x*blockDim.x + threadIdx.x) >> 5;
    int lane = threadIdx.x & 31;
    if (w >= BB) return;
    float s = 0.f;
    for (int f = lane; f < 128; f += 32) s = fmaf(g_b4[w*128 + f], oW[f], s);
    #pragma unroll
    for (int o=16;o;o>>=1) s += __shfl_xor_sync(0xffffffffu, s, o);
    if (lane == 0) out[w] = s + ob[0];
}

// ---------------- host wiring ----------------
static inline int cdiv(int a, int b){ return (a + b - 1) / b; }

extern "C" void kernel_launch(void* const* d_in, const int* in_sizes, int n_in,
                              void* d_out, int out_size)
{
    const float* x        = (const float*)d_in[0];
    const int*   ei       = (const int*)  d_in[1];
    const int*   batch    = (const int*)  d_in[2];
    const int*   target   = (const int*)  d_in[3];
    const float* gat_W    = (const float*)d_in[4];
    const float* gat_asr  = (const float*)d_in[5];
    const float* gat_ads  = (const float*)d_in[6];
    const float* gat_b    = (const float*)d_in[7];
    const float* gcn_W    = (const float*)d_in[8];
    const float* gcn_b    = (const float*)d_in[9];
    const float* fcg1_W   = (const float*)d_in[10];
    const float* fcg1_b   = (const float*)d_in[11];
    const float* fcg2_W   = (const float*)d_in[12];
    const float* fcg2_b   = (const float*)d_in[13];
    const float* emb      = (const float*)d_in[14];
    const float* cW       = (const float*)d_in[15];
    const float* cb       = (const float*)d_in[16];
    const float* fxt_W    = (const float*)d_in[17];
    const float* fxt_b    = (const float*)d_in[18];
    const float* f1_W     = (const float*)d_in[19];
    const float* f1_b     = (const float*)d_in[20];
    const float* f2_W     = (const float*)d_in[21];
    const float* f2_b     = (const float*)d_in[22];
    const float* f3_W     = (const float*)d_in[23];
    const float* f3_b     = (const float*)d_in[24];
    const float* f4_W     = (const float*)d_in[25];
    const float* f4_b     = (const float*)d_in[26];
    const float* o_W      = (const float*)d_in[27];
    const float* o_b      = (const float*)d_in[28];
    float* out            = (float*)d_out;

    float *p_h, *p_x1, *p_h2, *p_xg, *p_g1, *p_xc, *p_convf, *p_b1, *p_b2, *p_b3, *p_b4;
    int   *p_deg;
    cudaGetSymbolAddress((void**)&p_h,    g_h);
    cudaGetSymbolAddress((void**)&p_x1,   g_x1);
    cudaGetSymbolAddress((void**)&p_h2,   g_h2);
    cudaGetSymbolAddress((void**)&p_xg,   g_xg);
    cudaGetSymbolAddress((void**)&p_g1,   g_g1);
    cudaGetSymbolAddress((void**)&p_xc,   g_xc);
    cudaGetSymbolAddress((void**)&p_convf,g_convf);
    cudaGetSymbolAddress((void**)&p_b1,   g_b1);
    cudaGetSymbolAddress((void**)&p_b2,   g_b2);
    cudaGetSymbolAddress((void**)&p_b3,   g_b3);
    cudaGetSymbolAddress((void**)&p_b4,   g_b4);
    cudaGetSymbolAddress((void**)&p_deg,  g_deg);

    // --- graph branch ---
    gemm_k<false,false><<<dim3(cdiv(HID,64), cdiv(NN,64), 1), 256>>>(x, gat_W, nullptr, p_h, NN, HID, FF, HID, FF);
    gat_attn_k<<<cdiv(NN*HH*32, 256), 256>>>(gat_asr, gat_ads);
    zero_i<<<cdiv(NN,256),256>>>(p_deg, NN);
    deg_k<<<cdiv(EE,256),256>>>(ei);
    scan_k<<<1,1024>>>();
    fill_k<<<cdiv(EE,256),256>>>(ei);
    gat_agg_k<<<cdiv(NN*HH*32, 256), 256>>>(gat_b);
    gemm_k<false,false><<<dim3(cdiv(HID,64), cdiv(NN,64), 1), 256>>>(p_x1, gcn_W, nullptr, p_h2, NN, HID, HID, HID, HID);
    zero_f<<<cdiv(BB*HID,256),256>>>(p_xg, BB*HID);
    gcn_agg_pool_k<<<NN, 256>>>(gcn_b, batch);
    gemm_k<true,false><<<dim3(cdiv(1500,64), cdiv(BB,64), 1), 256>>>(p_xg, fcg1_W, fcg1_b, p_g1, BB, 1500, HID, 1500, HID);
    zero_f<<<cdiv(BB*256,256),256>>>(p_xc, BB*256);
    gemm_k<false,true><<<dim3(cdiv(128,64), cdiv(BB,64), 8), 256>>>(p_g1, fcg2_W, fcg2_b, p_xc, BB, 128, 1500, 256, 192);

    // --- protein branch ---
    protein_P_k<<<cdiv(VOC*NF*KS,256),256>>>(emb, cW);
    conv_k<<<cdiv(BB*NF*CONV_OUT,256),256>>>(target, cb);
    gemm_k<false,true><<<dim3(cdiv(128,64), cdiv(BB,64), 32), 256>>>(p_convf, fxt_W, fxt_b, p_xc + 128, BB, 128, CONVF, 256, 993);

    // --- fusion MLP ---
    gemm_k<true,false><<<dim3(cdiv(1024,64), cdiv(BB,64), 1), 256>>>(p_xc, f1_W, f1_b, p_b1, BB, 1024, 256, 1024, 256);
    gemm_k<true,false><<<dim3(cdiv(512,64),  cdiv(BB,64), 1), 256>>>(p_b1, f2_W, f2_b, p_b2, BB, 512, 1024, 512, 1024);
    gemm_k<true,false><<<dim3(cdiv(256,64),  cdiv(BB,64), 1), 256>>>(p_b2, f3_W, f3_b, p_b3, BB, 256, 512, 256, 512);
    gemm_k<true,false><<<dim3(cdiv(128,64),  cdiv(BB,64), 1), 256>>>(p_b3, f4_W, f4_b, p_b4, BB, 128, 256, 128, 256);
    out_k<<<cdiv(BB*32,256),256>>>(o_W, o_b, out);
}

// round 2
// speedup vs baseline: 1.0114x; 1.0114x over previous
#include <cuda_runtime.h>
#include <cuda_bf16.h>
#include <math.h>

// ---------------- problem constants ----------------
#define NN    20000
#define EE    400000
#define BB    200
#define HH    10
#define FF    78
#define HID   780          // HH*FF
#define SEQ   1000
#define VOC   26
#define EMB   128
#define NF    32
#define KS    8
#define CONV_OUT 993       // SEQ-KS+1
#define CONVF (NF*CONV_OUT)   // 31776

// ---------------- scratch (device globals; no runtime allocation) ----------------
__device__ float g_h   [(size_t)NN*HID];
__device__ float g_as  [NN*HH];
__device__ float g_ad  [NN*HH];
__device__ float g_x1  [(size_t)NN*HID];
__device__ float g_h2  [(size_t)NN*HID];
__device__ int   g_deg [NN];
__device__ float g_dinv[NN];
__device__ int   g_rowstart[NN+1];
__device__ int   g_cursor[NN];
__device__ int   g_csr [EE];
__device__ float g_xg  [BB*HID];
__device__ float g_g1  [BB*1500];
__device__ float g_xc  [BB*256];
__device__ float g_P   [VOC*NF*KS];
__device__ float g_convf[(size_t)BB*CONVF];
__device__ float g_b1  [BB*1024];
__device__ float g_b2  [BB*512];
__device__ float g_b3  [BB*256];
__device__ float g_b4  [BB*128];

__device__ __forceinline__ float lrelu(float x){ return x > 0.f ? x : 0.2f*x; }

__device__ __forceinline__ unsigned f2tf32(float f){
    unsigned u; asm("cvt.rna.tf32.f32 %0, %1;" : "=r"(u) : "f"(f)); return u;
}

__device__ __forceinline__ void mma_tf32(float* c, const unsigned* a, const unsigned* b){
    asm volatile("mma.sync.aligned.m16n8k8.row.col.f32.tf32.tf32.f32 "
        "{%0,%1,%2,%3}, {%4,%5,%6,%7}, {%8,%9}, {%0,%1,%2,%3};"
        : "+f"(c[0]),"+f"(c[1]),"+f"(c[2]),"+f"(c[3])
        : "r"(a[0]),"r"(a[1]),"r"(a[2]),"r"(a[3]), "r"(b[0]),"r"(b[1]));
}

// ---------------- tf32 tensor-core GEMM: C[M,N] = A[M,K] @ B[K,N] ----------------
// BM=128, BN=64, BK=16, 256 threads (8 warps in 4(M)x2(N)), warp tile 32x32.
// Double-buffered smem; A stored [m][k] stride 20, B stored [k][n] stride 72
// (both conflict-free for the m16n8k8 fragment access pattern).
template<bool VEC4>
__global__ void __launch_bounds__(256) gemm_tf32_k(
    const float* __restrict__ A, const float* __restrict__ B,
    float* __restrict__ C, int M, int N, int K)
{
    const int BM=128, BN=64, BK=16;
    const int AS=20, BS=72;
    __shared__ __align__(16) unsigned As[2][BM*AS];
    __shared__ __align__(16) unsigned Bs[2][BK*BS];

    const int tid = threadIdx.x;
    const int bm = blockIdx.y*BM, bn = blockIdx.x*BN;
    const int warp = tid>>5, lane = tid&31;
    const int wm = (warp&3)*32, wn = (warp>>2)*32;
    const int qr = lane>>2, qc = lane&3;

    float acc[2][4][4];
    #pragma unroll
    for (int i=0;i<2;i++)
        #pragma unroll
        for (int j=0;j<4;j++)
            #pragma unroll
            for (int l=0;l<4;l++) acc[i][j][l]=0.f;

    float pa[8]; float pb[4];

    // ---- prefetch tile k0 into registers ----
    auto loadTiles = [&](int k0){
        if (VEC4) {
            #pragma unroll
            for (int i=0;i<2;i++){
                int idx = tid + i*256;           // 0..511 float4 slots (A 128x16)
                int m = idx>>2, k4 = (idx&3)*4;
                int gm = bm+m, gk = k0+k4;
                float4 v = make_float4(0.f,0.f,0.f,0.f);
                if (gm < M){
                    if (gk+3 < K) v = *(const float4*)(A + (size_t)gm*K + gk);
                    else {
                        float t0=0,t1=0,t2=0,t3=0;
                        if (gk  <K) t0=A[(size_t)gm*K+gk];
                        if (gk+1<K) t1=A[(size_t)gm*K+gk+1];
                        if (gk+2<K) t2=A[(size_t)gm*K+gk+2];
                        if (gk+3<K) t3=A[(size_t)gm*K+gk+3];
                        v = make_float4(t0,t1,t2,t3);
                    }
                }
                pa[i*4+0]=v.x; pa[i*4+1]=v.y; pa[i*4+2]=v.z; pa[i*4+3]=v.w;
            }
            {
                int k = tid>>4, n4 = (tid&15)*4; // B 16x64, 256 float4 slots
                int gk = k0+k, gn = bn+n4;
                float4 v = make_float4(0.f,0.f,0.f,0.f);
                if (gk < K){
                    if (gn+3 < N) v = *(const float4*)(B + (size_t)gk*N + gn);
                    else {
                        float t0=0,t1=0,t2=0,t3=0;
                        if (gn  <N) t0=B[(size_t)gk*N+gn];
                        if (gn+1<N) t1=B[(size_t)gk*N+gn+1];
                        if (gn+2<N) t2=B[(size_t)gk*N+gn+2];
                        if (gn+3<N) t3=B[(size_t)gk*N+gn+3];
                        v = make_float4(t0,t1,t2,t3);
                    }
                }
                pb[0]=v.x; pb[1]=v.y; pb[2]=v.z; pb[3]=v.w;
            }
        } else {
            #pragma unroll
            for (int i=0;i<8;i++){
                int idx = tid + i*256;           // A 128x16 scalars
                int m = idx>>4, k = idx&15;
                int gm = bm+m, gk = k0+k;
                pa[i] = (gm<M && gk<K) ? A[(size_t)gm*K+gk] : 0.f;
            }
            #pragma unroll
            for (int i=0;i<4;i++){
                int idx = tid + i*256;           // B 16x64 scalars
                int k = idx>>6, n = idx&63;
                int gk = k0+k, gn = bn+n;
                pb[i] = (gk<K && gn<N) ? B[(size_t)gk*N+gn] : 0.f;
            }
        }
    };

    auto storeTiles = [&](int buf){
        if (VEC4) {
            #pragma unroll
            for (int i=0;i<2;i++){
                int idx = tid + i*256;
                int m = idx>>2, k4 = (idx&3)*4;
                uint4 v;
                v.x = f2tf32(pa[i*4+0]); v.y = f2tf32(pa[i*4+1]);
                v.z = f2tf32(pa[i*4+2]); v.w = f2tf32(pa[i*4+3]);
                *(uint4*)&As[buf][m*AS + k4] = v;
            }
            {
                int k = tid>>4, n4 = (tid&15)*4;
                uint4 v;
                v.x = f2tf32(pb[0]); v.y = f2tf32(pb[1]);
                v.z = f2tf32(pb[2]); v.w = f2tf32(pb[3]);
                *(uint4*)&Bs[buf][k*BS + n4] = v;
            }
        } else {
            #pragma unroll
            for (int i=0;i<8;i++){
                int idx = tid + i*256;
                int m = idx>>4, k = idx&15;
                As[buf][m*AS + k] = f2tf32(pa[i]);
            }
            #pragma unroll
            for (int i=0;i<4;i++){
                int idx = tid + i*256;
                int k = idx>>6, n = idx&63;
                Bs[buf][k*BS + n] = f2tf32(pb[i]);
            }
        }
    };

    const int nsteps = (K + BK - 1)/BK;
    loadTiles(0);
    storeTiles(0);
    __syncthreads();

    for (int s=0; s<nsteps; s++){
        int buf = s & 1;
        if (s+1 < nsteps) loadTiles((s+1)*BK);

        #pragma unroll
        for (int ks=0; ks<2; ks++){
            int k0 = ks*8;
            unsigned af[2][4], bf[4][2];
            #pragma unroll
            for (int tm=0; tm<2; tm++){
                int r = wm + tm*16 + qr;
                af[tm][0] = As[buf][(r  )*AS + k0 + qc    ];
                af[tm][1] = As[buf][(r+8)*AS + k0 + qc    ];
                af[tm][2] = As[buf][(r  )*AS + k0 + qc + 4];
                af[tm][3] = As[buf][(r+8)*AS + k0 + qc + 4];
            }
            #pragma unroll
            for (int tn=0; tn<4; tn++){
                int c = wn + tn*8 + qr;
                bf[tn][0] = Bs[buf][(k0+qc  )*BS + c];
                bf[tn][1] = Bs[buf][(k0+qc+4)*BS + c];
            }
            #pragma unroll
            for (int tm=0; tm<2; tm++)
                #pragma unroll
                for (int tn=0; tn<4; tn++)
                    mma_tf32(acc[tm][tn], af[tm], bf[tn]);
        }

        if (s+1 < nsteps){
            storeTiles((s+1)&1);
            __syncthreads();
        }
    }

    // epilogue
    #pragma unroll
    for (int tm=0; tm<2; tm++){
        #pragma unroll
        for (int tn=0; tn<4; tn++){
            int r = bm + wm + tm*16 + qr;
            int c = bn + wn + tn*8 + qc*2;
            float* cp = acc[tm][tn];
            if (r < M){
                if (c   < N) C[(size_t)r*N + c  ] = cp[0];
                if (c+1 < N) C[(size_t)r*N + c+1] = cp[1];
            }
            if (r+8 < M){
                if (c   < N) C[(size_t)(r+8)*N + c  ] = cp[2];
                if (c+1 < N) C[(size_t)(r+8)*N + c+1] = cp[3];
            }
        }
    }
}

// ---------------- generic tiled fp32 GEMM (small matrices) ----------------
template<bool RELU, bool ATOMIC>
__global__ void gemm_k(const float* __restrict__ A, const float* __restrict__ Bm,
                       const float* __restrict__ bias, float* __restrict__ C,
                       int M, int N, int K, int ldc, int kPerSplit)
{
    const int BM = 64, BN = 64, BK = 16;
    __shared__ float As[BK][BM+1];
    __shared__ float Bs[BK][BN+1];
    const int tid = threadIdx.x;
    const int brow = blockIdx.y * BM;
    const int bcol = blockIdx.x * BN;
    const int kz0 = blockIdx.z * kPerSplit;
    const int kz1 = min(K, kz0 + kPerSplit);
    const int tr = (tid >> 4) * 4;
    const int tc = (tid & 15) * 4;
    float acc[4][4];
    #pragma unroll
    for (int i=0;i<4;i++)
        #pragma unroll
        for (int j=0;j<4;j++) acc[i][j]=0.f;

    for (int k0 = kz0; k0 < kz1; k0 += BK) {
        #pragma unroll
        for (int i=0;i<4;i++){
            int idx = tid + i*256;
            int r = idx >> 4, c = idx & 15;
            int gr = brow + r, gc = k0 + c;
            float v = 0.f;
            if (gr < M && gc < kz1) v = A[(size_t)gr*K + gc];
            As[c][r] = v;
        }
        #pragma unroll
        for (int i=0;i<4;i++){
            int idx = tid + i*256;
            int r = idx >> 6, c = idx & 63;
            int gr = k0 + r, gc = bcol + c;
            float v = 0.f;
            if (gr < kz1 && gc < N) v = Bm[(size_t)gr*N + gc];
            Bs[r][c] = v;
        }
        __syncthreads();
        #pragma unroll
        for (int kk=0; kk<BK; kk++){
            float ra[4], rb[4];
            #pragma unroll
            for (int i=0;i<4;i++) ra[i] = As[kk][tr+i];
            #pragma unroll
            for (int j=0;j<4;j++) rb[j] = Bs[kk][tc+j];
            #pragma unroll
            for (int i=0;i<4;i++)
                #pragma unroll
                for (int j=0;j<4;j++) acc[i][j] = fmaf(ra[i], rb[j], acc[i][j]);
        }
        __syncthreads();
    }
    #pragma unroll
    for (int i=0;i<4;i++){
        int r = brow + tr + i;
        if (r >= M) continue;
        #pragma unroll
        for (int j=0;j<4;j++){
            int c = bcol + tc + j;
            if (c >= N) continue;
            float v = acc[i][j];
            if (ATOMIC) {
                if (blockIdx.z == 0 && bias) v += bias[c];
                atomicAdd(&C[(size_t)r*ldc + c], v);
            } else {
                if (bias) v += bias[c];
                if (RELU) v = fmaxf(v, 0.f);
                C[(size_t)r*ldc + c] = v;
            }
        }
    }
}

// ---------------- misc small kernels ----------------
__global__ void zero_f(float* p, int n){ int i = blockIdx.x*blockDim.x + threadIdx.x; if (i<n) p[i]=0.f; }
__global__ void zero_i(int* p, int n){ int i = blockIdx.x*blockDim.x + threadIdx.x; if (i<n) p[i]=0; }

__global__ void gat_attn_k(const float* __restrict__ a_src, const float* __restrict__ a_dst)
{
    int w = (blockIdx.x*blockDim.x + threadIdx.x) >> 5;
    int lane = threadIdx.x & 31;
    if (w >= NN*HH) return;
    int n = w / HH, hh = w % HH;
    const float* hp = g_h + (size_t)n*HID + hh*FF;
    float s1 = 0.f, s2 = 0.f;
    for (int f = lane; f < FF; f += 32){
        float v = hp[f];
        s1 = fmaf(v, a_src[hh*FF + f], s1);
        s2 = fmaf(v, a_dst[hh*FF + f], s2);
    }
    #pragma unroll
    for (int o=16;o;o>>=1){ s1 += __shfl_xor_sync(0xffffffffu, s1, o); s2 += __shfl_xor_sync(0xffffffffu, s2, o); }
    if (lane == 0){ g_as[w] = s1; g_ad[w] = s2; }
}

__global__ void deg_k(const int* __restrict__ ei){
    int e = blockIdx.x*blockDim.x + threadIdx.x;
    if (e >= EE) return;
    atomicAdd(&g_deg[ei[EE + e]], 1);
}

__global__ void scan_k(){
    __shared__ int part[1024];
    int tid = threadIdx.x;
    const int CH = (NN + 1023) / 1024;
    int base = tid * CH;
    int s = 0;
    for (int i=0;i<CH;i++){ int idx = base+i; if (idx < NN) s += g_deg[idx]; }
    part[tid] = s;
    __syncthreads();
    for (int off=1; off<1024; off<<=1){
        int v = 0;
        if (tid >= off) v = part[tid - off];
        __syncthreads();
        part[tid] += v;
        __syncthreads();
    }
    int run = (tid == 0) ? 0 : part[tid-1];
    for (int i=0;i<CH;i++){
        int idx = base + i;
        if (idx < NN){
            g_rowstart[idx] = run;
            g_cursor[idx]   = run;
            int d = g_deg[idx];
            run += d;
            g_dinv[idx] = rsqrtf((float)(d + 1));
        }
    }
    if (tid == 1023) g_rowstart[NN] = part[1023];
}

__global__ void fill_k(const int* __restrict__ ei){
    int e = blockIdx.x*blockDim.x + threadIdx.x;
    if (e >= EE) return;
    int d = ei[EE + e];
    int pos = atomicAdd(&g_cursor[d], 1);
    g_csr[pos] = ei[e];
}

__global__ void gat_agg_k(const float* __restrict__ gat_b)
{
    int w = (blockIdx.x*blockDim.x + threadIdx.x) >> 5;
    int lane = threadIdx.x & 31;
    if (w >= NN*HH) return;
    int n = w / HH, hh = w % HH;
    int rs = g_rowstart[n], re = g_rowstart[n+1];
    float adn = g_ad[n*HH + hh];
    float eself = lrelu(g_as[n*HH + hh] + adn);
    float m = eself;
    for (int i = rs + lane; i < re; i += 32){
        int s = g_csr[i];
        m = fmaxf(m, lrelu(g_as[s*HH + hh] + adn));
    }
    #pragma unroll
    for (int o=16;o;o>>=1) m = fmaxf(m, __shfl_xor_sync(0xffffffffu, m, o));
    float den = 0.f;
    for (int i = rs + lane; i < re; i += 32){
        int s = g_csr[i];
        den += __expf(lrelu(g_as[s*HH + hh] + adn) - m);
    }
    #pragma unroll
    for (int o=16;o;o>>=1) den += __shfl_xor_sync(0xffffffffu, den, o);
    den += __expf(eself - m);
    const int hb = hh * FF;
    float acc0, acc1, acc2 = 0.f;
    {
        float wgt = __expf(eself - m);
        const float* hp = g_h + (size_t)n*HID + hb;
        acc0 = wgt * hp[lane];
        acc1 = wgt * hp[lane + 32];
        if (lane + 64 < FF) acc2 = wgt * hp[lane + 64];
    }
    for (int i = rs; i < re; i++){
        int s = g_csr[i];
        float wgt = __expf(lrelu(g_as[s*HH + hh] + adn) - m);
        const float* hp = g_h + (size_t)s*HID + hb;
        acc0 = fmaf(wgt, hp[lane], acc0);
        acc1 = fmaf(wgt, hp[lane + 32], acc1);
        if (lane + 64 < FF) acc2 = fmaf(wgt, hp[lane + 64], acc2);
    }
    float inv = 1.f / den;
    float* xp = g_x1 + (size_t)n*HID + hb;
    xp[lane]      = fmaxf(acc0*inv + gat_b[hb + lane], 0.f);
    xp[lane + 32] = fmaxf(acc1*inv + gat_b[hb + lane + 32], 0.f);
    if (lane + 64 < FF) xp[lane + 64] = fmaxf(acc2*inv + gat_b[hb + lane + 64], 0.f);
}

__global__ void gcn_agg_pool_k(const float* __restrict__ gcn_b, const int* __restrict__ batch)
{
    int n = blockIdx.x;
    int tid = threadIdx.x;
    int rs = g_rowstart[n], re = g_rowstart[n+1];
    float dn = g_dinv[n];
    float acc[4] = {0.f,0.f,0.f,0.f};
    {
        float nm = dn * dn;
        const float* hp = g_h2 + (size_t)n*HID;
        #pragma unroll
        for (int k=0;k<4;k++){ int f = tid + k*256; if (f < HID) acc[k] = fmaf(nm, hp[f], acc[k]); }
    }
    for (int i = rs; i < re; i++){
        int s = g_csr[i];
        float nm = g_dinv[s] * dn;
        const float* hp = g_h2 + (size_t)s*HID;
        #pragma unroll
        for (int k=0;k<4;k++){ int f = tid + k*256; if (f < HID) acc[k] = fmaf(nm, hp[f], acc[k]); }
    }
    int b = batch[n];
    float* xp = g_xg + (size_t)b*HID;
    #pragma unroll
    for (int k=0;k<4;k++){
        int f = tid + k*256;
        if (f < HID) atomicAdd(&xp[f], fmaxf(acc[k] + gcn_b[f], 0.f));
    }
}

__global__ void protein_P_k(const float* __restrict__ emb, const float* __restrict__ cW)
{
    int idx = blockIdx.x*blockDim.x + threadIdx.x;
    if (idx >= VOC*NF*KS) return;
    int k  = idx % KS;
    int nf = (idx / KS) % NF;
    int v  = idx / (KS*NF);
    float s = 0.f;
    for (int e=0;e<EMB;e++) s = fmaf(emb[v*EMB + e], cW[(nf*EMB + e)*KS + k], s);
    g_P[idx] = s;
}

__global__ void conv_k(const int* __restrict__ target, const float* __restrict__ cb)
{
    int idx = blockIdx.x*blockDim.x + threadIdx.x;
    if (idx >= BB*NF*CONV_OUT) return;
    int t  = idx % CONV_OUT;
    int nf = (idx / CONV_OUT) % NF;
    int b  = idx / (CONV_OUT*NF);
    const int* tb = target + b*SEQ;
    float s = cb[nf];
    #pragma unroll
    for (int k=0;k<KS;k++) s += g_P[(tb[t+k]*NF + nf)*KS + k];
    g_convf[(size_t)b*CONVF + nf*CONV_OUT + t] = s;
}

__global__ void out_k(const float* __restrict__ oW, const float* __restrict__ ob, float* __restrict__ out)
{
    int w = (blockIdx.x*blockDim.x + threadIdx.x) >> 5;
    int lane = threadIdx.x & 31;
    if (w >= BB) return;
    float s = 0.f;
    for (int f = lane; f < 128; f += 32) s = fmaf(g_b4[w*128 + f], oW[f], s);
    #pragma unroll
    for (int o=16;o;o>>=1) s += __shfl_xor_sync(0xffffffffu, s, o);
    if (lane == 0) out[w] = s + ob[0];
}

// ---------------- host wiring ----------------
static inline int cdiv(int a, int b){ return (a + b - 1) / b; }

extern "C" void kernel_launch(void* const* d_in, const int* in_sizes, int n_in,
                              void* d_out, int out_size)
{
    const float* x        = (const float*)d_in[0];
    const int*   ei       = (const int*)  d_in[1];
    const int*   batch    = (const int*)  d_in[2];
    const int*   target   = (const int*)  d_in[3];
    const float* gat_W    = (const float*)d_in[4];
    const float* gat_asr  = (const float*)d_in[5];
    const float* gat_ads  = (const float*)d_in[6];
    const float* gat_b    = (const float*)d_in[7];
    const float* gcn_W    = (const float*)d_in[8];
    const float* gcn_b    = (const float*)d_in[9];
    const float* fcg1_W   = (const float*)d_in[10];
    const float* fcg1_b   = (const float*)d_in[11];
    const float* fcg2_W   = (const float*)d_in[12];
    const float* fcg2_b   = (const float*)d_in[13];
    const float* emb      = (const float*)d_in[14];
    const float* cW       = (const float*)d_in[15];
    const float* cb       = (const float*)d_in[16];
    const float* fxt_W    = (const float*)d_in[17];
    const float* fxt_b    = (const float*)d_in[18];
    const float* f1_W     = (const float*)d_in[19];
    const float* f1_b     = (const float*)d_in[20];
    const float* f2_W     = (const float*)d_in[21];
    const float* f2_b     = (const float*)d_in[22];
    const float* f3_W     = (const float*)d_in[23];
    const float* f3_b     = (const float*)d_in[24];
    const float* f4_W     = (const float*)d_in[25];
    const float* f4_b     = (const float*)d_in[26];
    const float* o_W      = (const float*)d_in[27];
    const float* o_b      = (const float*)d_in[28];
    float* out            = (float*)d_out;

    float *p_h, *p_x1, *p_h2, *p_xg, *p_g1, *p_xc, *p_convf, *p_b1, *p_b2, *p_b3, *p_b4;
    int   *p_deg;
    cudaGetSymbolAddress((void**)&p_h,    g_h);
    cudaGetSymbolAddress((void**)&p_x1,   g_x1);
    cudaGetSymbolAddress((void**)&p_h2,   g_h2);
    cudaGetSymbolAddress((void**)&p_xg,   g_xg);
    cudaGetSymbolAddress((void**)&p_g1,   g_g1);
    cudaGetSymbolAddress((void**)&p_xc,   g_xc);
    cudaGetSymbolAddress((void**)&p_convf,g_convf);
    cudaGetSymbolAddress((void**)&p_b1,   g_b1);
    cudaGetSymbolAddress((void**)&p_b2,   g_b2);
    cudaGetSymbolAddress((void**)&p_b3,   g_b3);
    cudaGetSymbolAddress((void**)&p_b4,   g_b4);
    cudaGetSymbolAddress((void**)&p_deg,  g_deg);

    // --- graph branch ---
    // h = x @ gat_W  (K=78, not /4 -> scalar path)
    gemm_tf32_k<false><<<dim3(cdiv(HID,64), cdiv(NN,128)), 256>>>(x, gat_W, p_h, NN, HID, FF);
    gat_attn_k<<<cdiv(NN*HH*32, 256), 256>>>(gat_asr, gat_ads);
    zero_i<<<cdiv(NN,256),256>>>(p_deg, NN);
    deg_k<<<cdiv(EE,256),256>>>(ei);
    scan_k<<<1,1024>>>();
    fill_k<<<cdiv(EE,256),256>>>(ei);
    gat_agg_k<<<cdiv(NN*HH*32, 256), 256>>>(gat_b);
    // h2 = x1 @ gcn_W  (K=780 divisible by 4 -> vectorized path)
    gemm_tf32_k<true><<<dim3(cdiv(HID,64), cdiv(NN,128)), 256>>>(p_x1, gcn_W, p_h2, NN, HID, HID);
    zero_f<<<cdiv(BB*HID,256),256>>>(p_xg, BB*HID);
    gcn_agg_pool_k<<<NN, 256>>>(gcn_b, batch);
    gemm_k<true,false><<<dim3(cdiv(1500,64), cdiv(BB,64), 1), 256>>>(p_xg, fcg1_W, fcg1_b, p_g1, BB, 1500, HID, 1500, HID);
    zero_f<<<cdiv(BB*256,256),256>>>(p_xc, BB*256);
    gemm_k<false,true><<<dim3(cdiv(128,64), cdiv(BB,64), 8), 256>>>(p_g1, fcg2_W, fcg2_b, p_xc, BB, 128, 1500, 256, 192);

    // --- protein branch ---
    protein_P_k<<<cdiv(VOC*NF*KS,256),256>>>(emb, cW);
    conv_k<<<cdiv(BB*NF*CONV_OUT,256),256>>>(target, cb);
    gemm_k<false,true><<<dim3(cdiv(128,64), cdiv(BB,64), 32), 256>>>(p_convf, fxt_W, fxt_b, p_xc + 128, BB, 128, CONVF, 256, 993);

    // --- fusion MLP ---
    gemm_k<true,false><<<dim3(cdiv(1024,64), cdiv(BB,64), 1), 256>>>(p_xc, f1_W, f1_b, p_b1, BB, 1024, 256, 1024, 256);
    gemm_k<true,false><<<dim3(cdiv(512,64),  cdiv(BB,64), 1), 256>>>(p_b1, f2_W, f2_b, p_b2, BB, 512, 1024, 512, 1024);
    gemm_k<true,false><<<dim3(cdiv(256,64),  cdiv(BB,64), 1), 256>>>(p_b2, f3_W, f3_b, p_b3, BB, 256, 512, 256, 512);
    gemm_k<true,false><<<dim3(cdiv(128,64),  cdiv(BB,64), 1), 256>>>(p_b3, f4_W, f4_b, p_b4, BB, 128, 256, 128, 256);
    out_k<<<cdiv(BB*32,256),256>>>(o_W, o_b, out);
}